// round 2
// baseline (speedup 1.0000x reference)
#include <cuda_runtime.h>
#include <math.h>

#define FULLMASK 0xffffffffu
#define LSZ 64
#define HSZ 32
#define BATCH 1024

// ---- packed f32x2 helpers (sm_103a) ----
__device__ __forceinline__ float2 ffma2(float2 a, float2 b, float2 c) {
    unsigned long long ua = reinterpret_cast<unsigned long long&>(a);
    unsigned long long ub = reinterpret_cast<unsigned long long&>(b);
    unsigned long long uc = reinterpret_cast<unsigned long long&>(c);
    asm("fma.rn.f32x2 %0, %1, %2, %0;" : "+l"(uc) : "l"(ua), "l"(ub));
    return reinterpret_cast<float2&>(uc);
}
__device__ __forceinline__ float2 fadd2(float2 a, float2 b) {
    unsigned long long ua = reinterpret_cast<unsigned long long&>(a);
    unsigned long long ub = reinterpret_cast<unsigned long long&>(b);
    unsigned long long ud;
    asm("add.rn.f32x2 %0, %1, %2;" : "=l"(ud) : "l"(ua), "l"(ub));
    return reinterpret_cast<float2&>(ud);
}

__global__ __launch_bounds__(32)
void rnn2d_kernel(const int*   __restrict__ x,     // [B,64,64]
                  const float* __restrict__ Win,   // [4,32]
                  const float* __restrict__ WcH,   // [32,32]
                  const float* __restrict__ WcV,   // [32,32]
                  const float* __restrict__ bV,    // [32]
                  const float* __restrict__ Wout,  // [32,2]
                  const float* __restrict__ bout,  // [2]
                  float*       __restrict__ out)   // [B]
{
    // carries stored in SCAN (snake-logical) order; double-buffered by row.
    __shared__ float s_c[2][LSZ][HSZ];
    __shared__ float s_wod[HSZ];

    const int lane = threadIdx.x;          // 0..31, owns hidden index `lane`
    const int b    = blockIdx.x;

    // ---- weights -> registers, k-pairs packed for f32x2 ----
    float2 WH[16], WV[16];
#pragma unroll
    for (int m = 0; m < 16; ++m) {
        WH[m] = make_float2(WcH[(2 * m) * HSZ + lane], WcH[(2 * m + 1) * HSZ + lane]);
        WV[m] = make_float2(WcV[(2 * m) * HSZ + lane], WcV[(2 * m + 1) * HSZ + lane]);
    }
    const float W0 = Win[lane], W1 = Win[HSZ + lane];
    const float W2 = Win[2 * HSZ + lane], W3 = Win[3 * HSZ + lane];
    const float bVl = bV[lane];
    s_wod[lane] = Wout[lane * 2 + 0] - Wout[lane * 2 + 1];
    const float bd = bout[0] - bout[1];

    // zero initial read buffer (row 0 reads buffer 0 = zeros)
#pragma unroll
    for (int c = 0; c < LSZ; ++c) s_c[0][c][lane] = 0.f;

    const int* xb = x + (size_t)b * (LSZ * LSZ);
    int cur0 = xb[lane];
    int cur1 = xb[HSZ + lane];
    unsigned long long rawprev = 0ull;
    float lanesum = 0.f;

    __syncwarp();

#pragma unroll 1
    for (int r = 0; r < LSZ; ++r) {
        // spin masks (bit p = spin at physical column p)
        unsigned int b0 = __ballot_sync(FULLMASK, cur0);
        unsigned int b1 = __ballot_sync(FULLMASK, cur1);
        unsigned long long raw = (unsigned long long)b0 |
                                 ((unsigned long long)b1 << 32);
        if (r < LSZ - 1) {                 // prefetch next row's spins
            cur0 = xb[(r + 1) * LSZ + lane];
            cur1 = xb[(r + 1) * LSZ + HSZ + lane];
        }
        const bool fwd = ((r & 1) == 0);
        // cm/pm: bit j = spin at scan position j (current / row above)
        const unsigned long long cm = fwd ? raw : __brevll(raw);
        const unsigned long long pm = fwd ? rawprev : __brevll(rawprev);
        rawprev = raw;
        const float eW2 = r ? W2 : 0.f;    // row 0: vertical one-hot is zero vec
        const float eW3 = r ? W3 : 0.f;

        const int rb = r & 1, wb = rb ^ 1;
        // prev-row carry at scan j lives at logical 63-j (snake mirror rule)
        const float4* rp = reinterpret_cast<const float4*>(&s_c[rb][LSZ - 1][0]);
        const float4* hp = reinterpret_cast<const float4*>(&s_c[wb][0][0]);
        float*        wp = &s_c[wb][0][lane];

        // ---- j = 0 (h = 0, no horizontal terms) ----
        {
            __syncwarp();
            float base = bVl + ((pm & 1ull) ? eW3 : eW2);
            float2 a0 = make_float2(0.f, 0.f), a1 = a0;
#pragma unroll
            for (int m = 0; m < 8; ++m) {
                float4 f = rp[m];
                a0 = ffma2(WV[2 * m],     make_float2(f.x, f.y), a0);
                a1 = ffma2(WV[2 * m + 1], make_float2(f.z, f.w), a1);
            }
            float2 s = fadd2(a0, a1);
            float v  = base + s.x + s.y;
            float ev = __expf(v) - 1.0f;
            wp[0] = (v > 0.f) ? v : ev;
            rp -= 8;
        }
        unsigned long long pmj = pm >> 1;
        unsigned long long cmj = cm;       // bit0 = sh for step j=1

        // ---- j = 1..63 ----
#pragma unroll 3
        for (int j = 1; j < LSZ; ++j) {
            __syncwarp();                  // h-vector of step j-1 now visible
            float hsel = (cmj & 1ull) ? W1 : W0;
            float vsel = (pmj & 1ull) ? eW3 : eW2;
            cmj >>= 1; pmj >>= 1;
            float base = bVl + hsel + vsel;
            float2 a0 = make_float2(0.f, 0.f), a1 = a0, c0 = a0, c1 = a0;
#pragma unroll
            for (int m = 0; m < 8; ++m) {
                float4 f = rp[m];          // vertical carry (prev row)
                float4 g = hp[m];          // h-vector (prev column)
                a0 = ffma2(WV[2 * m],     make_float2(f.x, f.y), a0);
                a1 = ffma2(WV[2 * m + 1], make_float2(f.z, f.w), a1);
                c0 = ffma2(WH[2 * m],     make_float2(g.x, g.y), c0);
                c1 = ffma2(WH[2 * m + 1], make_float2(g.z, g.w), c1);
            }
            float2 s = fadd2(fadd2(a0, a1), fadd2(c0, c1));
            float v  = base + s.x + s.y;
            float ev = __expf(v) - 1.0f;
            wp[j * HSZ] = (v > 0.f) ? v : ev;
            rp -= 8; hp += 8;
        }
        __syncwarp();                      // all columns stored before epilogue

        // ---- epilogue: delta = h . (Wout[:,0]-Wout[:,1]), XOR-rotated banks ----
        const float* hb = &s_c[wb][0][0];
        const int    l32 = lane * HSZ;
        float d0 = 0.f, d1 = 0.f;          // columns lane, lane+32 (scan order)
#pragma unroll
        for (int m = 0; m < 32; ++m) {
            int   idx = lane ^ m;          // conflict-free: bank = lane^m
            float w   = s_wod[idx];
            d0 = fmaf(hb[l32 + idx],              w, d0);
            d1 = fmaf(hb[l32 + HSZ * HSZ + idx],  w, d1);
        }
        float u0 = d0 + bd, u1 = d1 + bd;  // z0 - z1 per column
        int sp0 = (int)((cm >> lane) & 1ull);
        int sp1 = (int)((cm >> (lane + 32)) & 1ull);
        float t0 = sp0 ? u0 : -u0;         // lp = -log1p(exp(t)), stable form
        float t1 = sp1 ? u1 : -u1;
        float lp0 = -fmaxf(t0, 0.f) - log1pf(__expf(-fabsf(t0)));
        float lp1 = -fmaxf(t1, 0.f) - log1pf(__expf(-fabsf(t1)));
        if (isnan(lp0)) lp0 = -35.f;
        if (isnan(lp1)) lp1 = -35.f;
        lanesum += lp0 + lp1;
    }

    // final reduce across lanes
    float tot = lanesum;
#pragma unroll
    for (int off = 16; off; off >>= 1)
        tot += __shfl_xor_sync(FULLMASK, tot, off);
    if (lane == 0) out[b] = 0.5f * tot;
}

extern "C" void kernel_launch(void* const* d_in, const int* in_sizes, int n_in,
                              void* d_out, int out_size)
{
    const int*   x    = (const int*)  d_in[0];
    const float* Win  = (const float*)d_in[1];
    const float* WcH  = (const float*)d_in[2];
    const float* WcV  = (const float*)d_in[3];
    const float* bV   = (const float*)d_in[4];
    const float* Wout = (const float*)d_in[5];
    const float* bout = (const float*)d_in[6];

    rnn2d_kernel<<<BATCH, 32>>>(x, Win, WcH, WcV, bV, Wout, bout, (float*)d_out);
}